// round 3
// baseline (speedup 1.0000x reference)
#include <cuda_runtime.h>
#include <math.h>

#define NB   8
#define NC   256
#define LNC  19
#define HH   64
#define WW   64
#define SL   512
#define PIX  (HH*WW)
#define PD   68   // padded spatial (64 + 2*2)

typedef unsigned long long ull;

// ---------------- scratch (device globals: allocation-free) ----------------
static __device__ float g_mean[NB*NC];
static __device__ float g_rstd[NB*NC];
static __device__ int   g_labp[NB*PD*PD];          // padded label map, -1 = none/border
static __device__ float g_mu[NB*LNC*SL];           // relu(style @ fc_w + fc_b)
static __device__ float g_WshT[475*512];           // [j*25+i][k]
static __device__ float g_WspT[12800*512];         // [c*25+d][o2]  (spade gamma|beta)
static __device__ float g_WgbT[12800*512];         // [d*512+e][o2] (avg gamma|beta)
static __device__ float g_G[NB*LNC*25*512];        // [(b*19+j)*25+d][o2]
static __device__ float g_gavg[NB*PIX*512];        // [b*PIX+p][o2] gamma_avg|beta_avg (no bias)
static __device__ float g_actv1[NB*PIX*512];       // [b*PIX+p][k]
static __device__ float g_apad[NB*512*PD*PD];      // [b][k][PD][PD] zero-padded actv
static __device__ float g_gsp[NB*512*PIX];         // [b][o2][h][w] gamma_spade|beta_spade (with bias)

// ---------------- packed f32x2 helpers ----------------
__device__ __forceinline__ void fma_f32x2(ull& d, ull a, ull b) {
    asm("fma.rn.f32x2 %0, %1, %2, %0;" : "+l"(d) : "l"(a), "l"(b));
}
__device__ __forceinline__ ull pack_dup(float x) {
    ull r;
    asm("mov.b64 %0, {%1, %1};" : "=l"(r) : "f"(x));
    return r;
}
__device__ __forceinline__ ull pack2(float lo, float hi) {
    ull r;
    asm("mov.b64 %0, {%1, %2};" : "=l"(r) : "f"(lo), "f"(hi));
    return r;
}
__device__ __forceinline__ void unpack2(ull v, float& lo, float& hi) {
    asm("mov.b64 {%0, %1}, %2;" : "=f"(lo), "=f"(hi) : "l"(v));
}

// ---------------- instance norm stats ----------------
__global__ void k_stats(const float* __restrict__ x) {
    int bc = blockIdx.x;
    const float* p = x + (size_t)bc * PIX;
    float s = 0.f, ss = 0.f;
    for (int i = threadIdx.x; i < PIX; i += 256) { float v = p[i]; s += v; ss += v * v; }
    __shared__ float sh[512];
    sh[threadIdx.x] = s; sh[256 + threadIdx.x] = ss; __syncthreads();
    for (int off = 128; off > 0; off >>= 1) {
        if (threadIdx.x < off) { sh[threadIdx.x] += sh[threadIdx.x + off]; sh[256 + threadIdx.x] += sh[256 + threadIdx.x + off]; }
        __syncthreads();
    }
    if (threadIdx.x == 0) {
        float m = sh[0] / (float)PIX;
        float v = sh[256] / (float)PIX - m * m;
        g_mean[bc] = m; g_rstd[bc] = rsqrtf(v + 1e-5f);
    }
}

// ---------------- padded label map ----------------
__global__ void k_labels(const float* __restrict__ segmap) {
    int idx = blockIdx.x * 256 + threadIdx.x;
    if (idx >= NB * PD * PD) return;
    int b = idx / (PD * PD), rem = idx % (PD * PD);
    int y = rem / PD, xx = rem % PD;
    int lab = -1;
    if (y >= 2 && y < 66 && xx >= 2 && xx < 66) {
        int h = y - 2, w = xx - 2;
        for (int j = LNC - 1; j >= 0; j--) {
            if (segmap[((b * LNC + j) * HH + h) * WW + w] > 0.f) { lab = j; break; }
        }
    }
    g_labp[idx] = lab;
}

// ---------------- mu = relu(style @ fc_w + fc_b) ----------------
__global__ void k_mu(const float* __restrict__ style, const float* __restrict__ fc_w,
                     const float* __restrict__ fc_b) {
    int bj = blockIdx.x;           // 0..151
    int b = bj / LNC, j = bj % LNC;
    int tid = threadIdx.x, lane = tid & 31, wid = tid >> 5;
    __shared__ float sc[SL];
    for (int i = tid; i < SL; i += 256) sc[i] = style[(b * LNC + j) * SL + i];
    __syncthreads();
    for (int e = wid; e < SL; e += 8) {
        const float* row = fc_w + ((size_t)(j * SL + e)) * SL;
        float acc = 0.f;
        for (int d = lane; d < SL; d += 32) acc += sc[d] * row[d];
        for (int off = 16; off; off >>= 1) acc += __shfl_xor_sync(0xffffffffu, acc, off);
        if (lane == 0) {
            float v = acc + fc_b[j * SL + e];
            g_mu[(b * LNC + j) * SL + e] = fmaxf(v, 0.f);
        }
    }
}

// ---------------- generic tiled transpose ----------------
__global__ void k_transpose(const float* __restrict__ in, float* __restrict__ out,
                            int M, int N, int outStride, int colOff, int mode) {
    __shared__ float t[32][33];
    int n0 = blockIdx.x * 32, m0 = blockIdx.y * 32;
    int tx = threadIdx.x, ty = threadIdx.y;
    for (int r = ty; r < 32; r += 8) {
        int m = m0 + r, n = n0 + tx;
        t[r][tx] = (m < M && n < N) ? in[(size_t)m * N + n] : 0.f;
    }
    __syncthreads();
    for (int r = ty; r < 32; r += 8) {
        int n = n0 + r, m = m0 + tx;
        if (n < N && m < M) {
            int orow = (mode == 1) ? (n % 25) * 512 + (n / 25) : n;
            out[(size_t)orow * outStride + colOff + m] = t[tx][r];
        }
    }
}

// ---------------- G[b,j,d,o2] = sum_e WgbT[d,e,o2] * mu[b,j,e] ----------------
__global__ void k_G() {
    __shared__ float mus[4 * SL];
    int bj0 = blockIdx.x * 4;
    int off = blockIdx.y;            // 0..24
    int tid = threadIdx.x;
    for (int i = tid; i < 4 * SL; i += 256) mus[i] = g_mu[bj0 * SL + i];
    __syncthreads();
    float a0g = 0, a0b = 0, a1g = 0, a1b = 0, a2g = 0, a2b = 0, a3g = 0, a3b = 0;
    const float* wrow = g_WgbT + (size_t)off * 512 * 512;
    for (int e = 0; e < 512; e++) {
        float wa = wrow[e * 512 + tid];
        float wb = wrow[e * 512 + tid + 256];
        float m0 = mus[e], m1 = mus[512 + e], m2 = mus[1024 + e], m3 = mus[1536 + e];
        a0g += m0 * wa; a0b += m0 * wb;
        a1g += m1 * wa; a1b += m1 * wb;
        a2g += m2 * wa; a2b += m2 * wb;
        a3g += m3 * wa; a3b += m3 * wb;
    }
    float* o0 = g_G + ((size_t)((bj0 + 0) * 25 + off)) * 512;
    float* o1 = g_G + ((size_t)((bj0 + 1) * 25 + off)) * 512;
    float* o2 = g_G + ((size_t)((bj0 + 2) * 25 + off)) * 512;
    float* o3 = g_G + ((size_t)((bj0 + 3) * 25 + off)) * 512;
    o0[tid] = a0g; o0[tid + 256] = a0b;
    o1[tid] = a1g; o1[tid + 256] = a1b;
    o2[tid] = a2g; o2[tid + 256] = a2b;
    o3[tid] = a3g; o3[tid + 256] = a3b;
}

// ---------------- gather: gavg[b,p,o2] = sum over 25 window offsets of G ----------------
__global__ void k_gather() {
    int bh = blockIdx.x;
    int b = bh >> 6, h = bh & 63;
    int tid = threadIdx.x;
    __shared__ int labw[5 * PD];
    for (int i = tid; i < 5 * PD; i += 256)
        labw[i] = g_labp[(b * PD + h + i / PD) * PD + (i % PD)];
    __syncthreads();
    for (int w = 0; w < WW; w++) {
        float a0 = 0.f, a1 = 0.f;
        #pragma unroll
        for (int i = 0; i < 25; i++) {
            int j = labw[(i / 5) * PD + w + (i % 5)];
            if (j >= 0) {
                const float* g = g_G + ((size_t)((b * LNC + j) * 25 + i)) * 512;
                a0 += g[tid]; a1 += g[tid + 256];
            }
        }
        float* o = g_gavg + ((size_t)(b * PIX + h * WW + w)) * 512;
        o[tid] = a0; o[tid + 256] = a1;
    }
}

// ---------------- actv[b,p,k] = relu(sh_b[k] + sum_i WshT[L*25+i][k]) ----------------
__global__ void k_actv(const float* __restrict__ sh_b) {
    int bh = blockIdx.x;
    int b = bh >> 6, h = bh & 63;
    int tid = threadIdx.x;
    __shared__ int labw[5 * PD];
    for (int i = tid; i < 5 * PD; i += 256)
        labw[i] = g_labp[(b * PD + h + i / PD) * PD + (i % PD)];
    __syncthreads();
    float bias0 = sh_b[tid], bias1 = sh_b[tid + 256];
    for (int w = 0; w < WW; w++) {
        float a0 = bias0, a1 = bias1;
        #pragma unroll
        for (int i = 0; i < 25; i++) {
            int j = labw[(i / 5) * PD + w + (i % 5)];
            if (j >= 0) {
                const float* g = g_WshT + ((size_t)(j * 25 + i)) * 512;
                a0 += g[tid]; a1 += g[tid + 256];
            }
        }
        float* o = g_actv1 + ((size_t)(b * PIX + h * WW + w)) * 512;
        o[tid] = fmaxf(a0, 0.f); o[tid + 256] = fmaxf(a1, 0.f);
    }
}

// ---------------- zero padded-activation borders ----------------
__global__ void k_border() {
    int idx = blockIdx.x * 256 + threadIdx.x;
    if (idx >= NB * 512 * PD * PD) return;
    int rem = idx % (PD * PD);
    int y = rem / PD, xx = rem % PD;
    if (y < 2 || y >= 66 || xx < 2 || xx >= 66) g_apad[idx] = 0.f;
}

// ---------------- transpose actv [b,p,k] -> apad [b,k,PD,PD] interior ----------------
__global__ void k_atrans() {
    __shared__ float t[32][33];
    int p0 = blockIdx.x * 32, k0 = blockIdx.y * 32, b = blockIdx.z;
    int tx = threadIdx.x, ty = threadIdx.y;
    for (int r = ty; r < 32; r += 8)
        t[r][tx] = g_actv1[((size_t)(b * PIX + p0 + r)) * 512 + k0 + tx];
    __syncthreads();
    for (int r = ty; r < 32; r += 8) {
        int k = k0 + r, p = p0 + tx;
        int h = p >> 6, w = p & 63;
        g_apad[((size_t)(b * 512 + k) * PD + (h + 2)) * PD + (w + 2)] = t[tx][r];
    }
}

// ---------------- fused spade conv (f32x2 packed FMA core) ----------------
// gsp[b,o2,h,w] (o2<256: gamma, else beta), biases included.
__global__ void __launch_bounds__(256, 2)
k_conv(const float* __restrict__ sgb, const float* __restrict__ sbb) {
    __shared__ float Ws[2 * 25 * 128];   // [c][25][128]  25.6 KB
    __shared__ float As[2 * 6 * PD];     // [c][6][68]     3.3 KB
    int ob = blockIdx.x;                 // 0..3   (o2 tile of 128)
    int h0 = blockIdx.y * 2;             // 0..62  (2 output rows)
    int b  = blockIdx.z;
    int tid = threadIdx.x;
    int ty = tid >> 4;                   // 0..15  o-group (8 o2 each)
    int tx = tid & 15;
    int hh = tx >> 3;                    // 0/1 output row within tile
    int wg = tx & 7;                     // 0..7 px-group (8 px each)
    int o0 = ob * 128;
    int obase = o0 + (ty << 3);

    // acc2[q][pi]: packed accumulators for channels (obase+2q, obase+2q+1), pixel pi
    ull acc2[4][8];
    #pragma unroll
    for (int q = 0; q < 4; q++) {
        int olo = obase + 2 * q;
        float blo = (olo < 256) ? sgb[olo] : sbb[olo - 256];
        float bhi = (olo + 1 < 256) ? sgb[olo + 1] : sbb[olo + 1 - 256];
        ull bp = pack2(blo, bhi);
        #pragma unroll
        for (int pi = 0; pi < 8; pi++) acc2[q][pi] = bp;
    }

    for (int c0 = 0; c0 < 512; c0 += 2) {
        for (int idx = tid; idx < 6400; idx += 256) {
            int c = idx / 3200, rem = idx % 3200;
            Ws[idx] = g_WspT[((size_t)((c0 + c) * 25 + rem / 128)) * 512 + o0 + (rem & 127)];
        }
        for (int idx = tid; idx < 816; idx += 256) {
            int c = idx / 408, rem = idx % 408;
            As[idx] = g_apad[((size_t)(b * 512 + c0 + c) * PD + (h0 + rem / PD)) * PD + (rem % PD)];
        }
        __syncthreads();
        #pragma unroll
        for (int c = 0; c < 2; c++) {
            #pragma unroll 1
            for (int ky = 0; ky < 5; ky++) {
                const float4* ap = (const float4*)&As[(c * 6 + hh + ky) * PD + (wg << 3)];
                float4 A0 = ap[0], A1 = ap[1], A2 = ap[2];
                ull ad[12];
                ad[0] = pack_dup(A0.x); ad[1] = pack_dup(A0.y);
                ad[2] = pack_dup(A0.z); ad[3] = pack_dup(A0.w);
                ad[4] = pack_dup(A1.x); ad[5] = pack_dup(A1.y);
                ad[6] = pack_dup(A1.z); ad[7] = pack_dup(A1.w);
                ad[8] = pack_dup(A2.x); ad[9] = pack_dup(A2.y);
                ad[10] = pack_dup(A2.z); ad[11] = pack_dup(A2.w);
                // thread's 8 weights per kx start at (c*25+ky*5+kx)*128 + ty*8
                const ulonglong2* wb =
                    (const ulonglong2*)&Ws[(c * 25 + ky * 5) * 128 + (ty << 3)];
                #pragma unroll
                for (int kx = 0; kx < 5; kx++) {
                    // 128 floats per kx row = 32 ulonglong2; thread slice = 2 ulonglong2
                    ulonglong2 wA = wb[kx * 32];      // q0, q1
                    ulonglong2 wB = wb[kx * 32 + 1];  // q2, q3
                    #pragma unroll
                    for (int pi = 0; pi < 8; pi++) {
                        ull a = ad[kx + pi];
                        fma_f32x2(acc2[0][pi], wA.x, a);
                        fma_f32x2(acc2[1][pi], wA.y, a);
                        fma_f32x2(acc2[2][pi], wB.x, a);
                        fma_f32x2(acc2[3][pi], wB.y, a);
                    }
                }
            }
        }
        __syncthreads();
    }

    int hout = h0 + hh;
    #pragma unroll
    for (int q = 0; q < 4; q++) {
        float lo[8], hi[8];
        #pragma unroll
        for (int pi = 0; pi < 8; pi++) unpack2(acc2[q][pi], lo[pi], hi[pi]);
        float* oplo = &g_gsp[((size_t)(b * 512 + obase + 2 * q) * HH + hout) * WW + (wg << 3)];
        float* ophi = &g_gsp[((size_t)(b * 512 + obase + 2 * q + 1) * HH + hout) * WW + (wg << 3)];
        float4 l0 = {lo[0], lo[1], lo[2], lo[3]}, l1 = {lo[4], lo[5], lo[6], lo[7]};
        float4 h0v = {hi[0], hi[1], hi[2], hi[3]}, h1v = {hi[4], hi[5], hi[6], hi[7]};
        ((float4*)oplo)[0] = l0; ((float4*)oplo)[1] = l1;
        ((float4*)ophi)[0] = h0v; ((float4*)ophi)[1] = h1v;
    }
}

// ---------------- final blend ----------------
__global__ void k_final(const float* __restrict__ x,
                        const float* __restrict__ cgb, const float* __restrict__ cbb,
                        const float* __restrict__ bg, const float* __restrict__ bb,
                        float* __restrict__ out) {
    int bh = blockIdx.x;
    int b = bh >> 6, h = bh & 63;
    int tid = threadIdx.x;
    int w = tid & 63, os = tid >> 6;     // os in [0,4)
    float ga = 1.f / (1.f + expf(-bg[0]));
    float ba = 1.f / (1.f + expf(-bb[0]));
    size_t gi = ((size_t)(b * PIX + h * WW + w)) * 512;
    for (int oc = 0; oc < NC; oc += 4) {
        int o = oc + os;
        float m = g_mean[b * NC + o], rs = g_rstd[b * NC + o];
        size_t xi = ((size_t)(b * NC + o) * HH + h) * WW + w;
        float nv = (x[xi] - m) * rs;
        float gs = g_gsp[((size_t)(b * 512 + o) * HH + h) * WW + w];
        float bs = g_gsp[((size_t)(b * 512 + o + 256) * HH + h) * WW + w];
        float gav = g_gavg[gi + o] + cgb[o];
        float bav = g_gavg[gi + 256 + o] + cbb[o];
        float gf = ga * gav + (1.f - ga) * gs;
        float bf = ba * bav + (1.f - ba) * bs;
        out[xi] = nv * (1.f + gf) + bf;
    }
}

// ---------------- launch ----------------
extern "C" void kernel_launch(void* const* d_in, const int* in_sizes, int n_in,
                              void* d_out, int out_size) {
    const float* x      = (const float*)d_in[0];
    const float* segmap = (const float*)d_in[1];
    const float* style  = (const float*)d_in[2];
    const float* fc_w   = (const float*)d_in[3];
    const float* fc_b   = (const float*)d_in[4];
    const float* cgw    = (const float*)d_in[5];
    const float* cgb    = (const float*)d_in[6];
    const float* cbw    = (const float*)d_in[7];
    const float* cbb    = (const float*)d_in[8];
    const float* ssw    = (const float*)d_in[9];
    const float* ssb    = (const float*)d_in[10];
    const float* sgw    = (const float*)d_in[11];
    const float* sgb    = (const float*)d_in[12];
    const float* sbw    = (const float*)d_in[13];
    const float* sbb    = (const float*)d_in[14];
    const float* bg     = (const float*)d_in[15];
    const float* bb     = (const float*)d_in[16];
    float* out = (float*)d_out;

    float* pWshT; cudaGetSymbolAddress((void**)&pWshT, g_WshT);
    float* pWspT; cudaGetSymbolAddress((void**)&pWspT, g_WspT);
    float* pWgbT; cudaGetSymbolAddress((void**)&pWgbT, g_WgbT);

    dim3 tb(32, 8);

    k_stats<<<NB * NC, 256>>>(x);
    k_labels<<<(NB * PD * PD + 255) / 256, 256>>>(segmap);
    k_mu<<<NB * LNC, 256>>>(style, fc_w, fc_b);

    k_transpose<<<dim3(15, 16), tb>>>(ssw, pWshT, 512, 475, 512, 0, 0);
    k_transpose<<<dim3(400, 8), tb>>>(sgw, pWspT, 256, 12800, 512, 0, 0);
    k_transpose<<<dim3(400, 8), tb>>>(sbw, pWspT, 256, 12800, 512, 256, 0);
    k_transpose<<<dim3(400, 8), tb>>>(cgw, pWgbT, 256, 12800, 512, 0, 1);
    k_transpose<<<dim3(400, 8), tb>>>(cbw, pWgbT, 256, 12800, 512, 256, 1);

    k_G<<<dim3(38, 25), 256>>>();
    k_gather<<<NB * HH, 256>>>();
    k_actv<<<NB * HH, 256>>>(ssb);
    k_border<<<(NB * 512 * PD * PD + 255) / 256, 256>>>();
    k_atrans<<<dim3(PIX / 32, 512 / 32, NB), tb>>>();
    k_conv<<<dim3(4, 32, NB), 256>>>(sgb, sbb);
    k_final<<<NB * HH, 256>>>(x, cgb, cbb, bg, bb, out);
}

// round 4
// speedup vs baseline: 3.2392x; 3.2392x over previous
#include <cuda_runtime.h>
#include <math.h>

#define NB   8
#define NC   256
#define LNC  19
#define HH   64
#define WW   64
#define SL   512
#define PIX  (HH*WW)
#define PD   68

typedef unsigned long long ull;

// ---------------- scratch ----------------
static __device__ float g_mean[NB*NC];
static __device__ float g_rstd[NB*NC];
static __device__ int   g_labp[NB*PD*PD];
static __device__ float g_mu[NB*LNC*SL];
static __device__ float g_WshT[475*512];           // [j*25+i][k]
static __device__ float g_WspT[12800*512];         // [c*25+d][o2] (tf32-rounded)
static __device__ float g_WgbT[12800*512];         // [d*512+e][o2]
static __device__ float g_G[NB*LNC*25*512];
static __device__ float g_gavg[NB*PIX*512];
static __device__ float g_actv1[NB*PIX*512];
static __device__ float g_apad[NB*512*PD*PD];      // tf32-rounded interior
static __device__ float g_gsp[NB*512*PIX];

// ---------------- helpers ----------------
__device__ __forceinline__ void fma_f32x2(ull& d, ull a, ull b) {
    asm("fma.rn.f32x2 %0, %1, %2, %0;" : "+l"(d) : "l"(a), "l"(b));
}
__device__ __forceinline__ ull pack_dup(float x) {
    ull r; asm("mov.b64 %0, {%1, %1};" : "=l"(r) : "f"(x)); return r;
}
__device__ __forceinline__ ull pack2(float lo, float hi) {
    ull r; asm("mov.b64 %0, {%1, %2};" : "=l"(r) : "f"(lo), "f"(hi)); return r;
}
__device__ __forceinline__ void unpack2(ull v, float& lo, float& hi) {
    asm("mov.b64 {%0, %1}, %2;" : "=f"(lo), "=f"(hi) : "l"(v));
}
__device__ __forceinline__ float tf32r(float x) {
    unsigned u; asm("cvt.rna.tf32.f32 %0, %1;" : "=r"(u) : "f"(x));
    return __uint_as_float(u);
}
__device__ __forceinline__ void mma_tf32(float4& d, const unsigned* a,
                                         unsigned b0, unsigned b1) {
    asm("mma.sync.aligned.m16n8k8.row.col.f32.tf32.tf32.f32 "
        "{%0,%1,%2,%3}, {%4,%5,%6,%7}, {%8,%9}, {%0,%1,%2,%3};"
        : "+f"(d.x), "+f"(d.y), "+f"(d.z), "+f"(d.w)
        : "r"(a[0]), "r"(a[1]), "r"(a[2]), "r"(a[3]), "r"(b0), "r"(b1));
}
__device__ __forceinline__ void cpa16(float* dst, const float* src) {
    unsigned s = (unsigned)__cvta_generic_to_shared(dst);
    asm volatile("cp.async.cg.shared.global [%0], [%1], 16;" :: "r"(s), "l"(src) : "memory");
}
__device__ __forceinline__ void cpa_commit() {
    asm volatile("cp.async.commit_group;" ::: "memory");
}
__device__ __forceinline__ void cpa_wait0() {
    asm volatile("cp.async.wait_group 0;" ::: "memory");
}

// ---------------- instance norm stats ----------------
__global__ void k_stats(const float* __restrict__ x) {
    int bc = blockIdx.x;
    const float* p = x + (size_t)bc * PIX;
    float s = 0.f, ss = 0.f;
    for (int i = threadIdx.x; i < PIX; i += 256) { float v = p[i]; s += v; ss += v * v; }
    __shared__ float sh[512];
    sh[threadIdx.x] = s; sh[256 + threadIdx.x] = ss; __syncthreads();
    for (int off = 128; off > 0; off >>= 1) {
        if (threadIdx.x < off) { sh[threadIdx.x] += sh[threadIdx.x + off]; sh[256 + threadIdx.x] += sh[256 + threadIdx.x + off]; }
        __syncthreads();
    }
    if (threadIdx.x == 0) {
        float m = sh[0] / (float)PIX;
        float v = sh[256] / (float)PIX - m * m;
        g_mean[bc] = m; g_rstd[bc] = rsqrtf(v + 1e-5f);
    }
}

// ---------------- padded label map ----------------
__global__ void k_labels(const float* __restrict__ segmap) {
    int idx = blockIdx.x * 256 + threadIdx.x;
    if (idx >= NB * PD * PD) return;
    int b = idx / (PD * PD), rem = idx % (PD * PD);
    int y = rem / PD, xx = rem % PD;
    int lab = -1;
    if (y >= 2 && y < 66 && xx >= 2 && xx < 66) {
        int h = y - 2, w = xx - 2;
        for (int j = LNC - 1; j >= 0; j--) {
            if (segmap[((b * LNC + j) * HH + h) * WW + w] > 0.f) { lab = j; break; }
        }
    }
    g_labp[idx] = lab;
}

// ---------------- mu ----------------
__global__ void k_mu(const float* __restrict__ style, const float* __restrict__ fc_w,
                     const float* __restrict__ fc_b) {
    int bj = blockIdx.x;
    int b = bj / LNC, j = bj % LNC;
    int tid = threadIdx.x, lane = tid & 31, wid = tid >> 5;
    __shared__ float sc[SL];
    for (int i = tid; i < SL; i += 256) sc[i] = style[(b * LNC + j) * SL + i];
    __syncthreads();
    for (int e = wid; e < SL; e += 8) {
        const float* row = fc_w + ((size_t)(j * SL + e)) * SL;
        float acc = 0.f;
        for (int d = lane; d < SL; d += 32) acc += sc[d] * row[d];
        for (int off = 16; off; off >>= 1) acc += __shfl_xor_sync(0xffffffffu, acc, off);
        if (lane == 0) {
            float v = acc + fc_b[j * SL + e];
            g_mu[(b * LNC + j) * SL + e] = fmaxf(v, 0.f);
        }
    }
}

// ---------------- tiled transpose (optional tf32 rounding) ----------------
__global__ void k_transpose(const float* __restrict__ in, float* __restrict__ out,
                            int M, int N, int outStride, int colOff, int mode, int rnd) {
    __shared__ float t[32][33];
    int n0 = blockIdx.x * 32, m0 = blockIdx.y * 32;
    int tx = threadIdx.x, ty = threadIdx.y;
    for (int r = ty; r < 32; r += 8) {
        int m = m0 + r, n = n0 + tx;
        t[r][tx] = (m < M && n < N) ? in[(size_t)m * N + n] : 0.f;
    }
    __syncthreads();
    for (int r = ty; r < 32; r += 8) {
        int n = n0 + r, m = m0 + tx;
        if (n < N && m < M) {
            int orow = (mode == 1) ? (n % 25) * 512 + (n / 25) : n;
            float v = t[tx][r];
            if (rnd) v = tf32r(v);
            out[(size_t)orow * outStride + colOff + m] = v;
        }
    }
}

// ---------------- k_G: G[b,j,d,o2] = sum_e WgbT[d,e,o2] * mu[b,j,e] (FFMA2, 8-bj) --------
__global__ void k_G() {
    __shared__ float mus[8 * SL];
    int bj0 = blockIdx.x * 8;        // 19 blocks of 8 = 152
    int off = blockIdx.y;            // 0..24
    int tid = threadIdx.x;           // 128 threads, o2 quad = 4*tid
    for (int i = tid; i < 8 * SL; i += 128) mus[i] = g_mu[bj0 * SL + i];
    __syncthreads();
    ull acc[8][2];
    #pragma unroll
    for (int j = 0; j < 8; j++) { acc[j][0] = 0ull; acc[j][1] = 0ull; }
    const float4* wrow = (const float4*)(g_WgbT + (size_t)off * 512 * 512);
    for (int e = 0; e < 512; e++) {
        float4 w = wrow[e * 128 + tid];
        ull wp0 = pack2(w.x, w.y), wp1 = pack2(w.z, w.w);
        #pragma unroll
        for (int j = 0; j < 8; j++) {
            ull m = pack_dup(mus[j * 512 + e]);
            fma_f32x2(acc[j][0], wp0, m);
            fma_f32x2(acc[j][1], wp1, m);
        }
    }
    #pragma unroll
    for (int j = 0; j < 8; j++) {
        float4 o;
        unpack2(acc[j][0], o.x, o.y);
        unpack2(acc[j][1], o.z, o.w);
        *(float4*)&g_G[((size_t)((bj0 + j) * 25 + off)) * 512 + 4 * tid] = o;
    }
}

// ---------------- gather ----------------
__global__ void k_gather() {
    int bh = blockIdx.x;
    int b = bh >> 6, h = bh & 63;
    int tid = threadIdx.x;
    __shared__ int labw[5 * PD];
    for (int i = tid; i < 5 * PD; i += 256)
        labw[i] = g_labp[(b * PD + h + i / PD) * PD + (i % PD)];
    __syncthreads();
    for (int w = 0; w < WW; w++) {
        float a0 = 0.f, a1 = 0.f;
        #pragma unroll
        for (int i = 0; i < 25; i++) {
            int j = labw[(i / 5) * PD + w + (i % 5)];
            if (j >= 0) {
                const float* g = g_G + ((size_t)((b * LNC + j) * 25 + i)) * 512;
                a0 += g[tid]; a1 += g[tid + 256];
            }
        }
        float* o = g_gavg + ((size_t)(b * PIX + h * WW + w)) * 512;
        o[tid] = a0; o[tid + 256] = a1;
    }
}

// ---------------- actv ----------------
__global__ void k_actv(const float* __restrict__ sh_b) {
    int bh = blockIdx.x;
    int b = bh >> 6, h = bh & 63;
    int tid = threadIdx.x;
    __shared__ int labw[5 * PD];
    for (int i = tid; i < 5 * PD; i += 256)
        labw[i] = g_labp[(b * PD + h + i / PD) * PD + (i % PD)];
    __syncthreads();
    float bias0 = sh_b[tid], bias1 = sh_b[tid + 256];
    for (int w = 0; w < WW; w++) {
        float a0 = bias0, a1 = bias1;
        #pragma unroll
        for (int i = 0; i < 25; i++) {
            int j = labw[(i / 5) * PD + w + (i % 5)];
            if (j >= 0) {
                const float* g = g_WshT + ((size_t)(j * 25 + i)) * 512;
                a0 += g[tid]; a1 += g[tid + 256];
            }
        }
        float* o = g_actv1 + ((size_t)(b * PIX + h * WW + w)) * 512;
        o[tid] = fmaxf(a0, 0.f); o[tid + 256] = fmaxf(a1, 0.f);
    }
}

// ---------------- zero padded borders ----------------
__global__ void k_border() {
    int idx = blockIdx.x * 256 + threadIdx.x;
    if (idx >= NB * 512 * PD * PD) return;
    int rem = idx % (PD * PD);
    int y = rem / PD, xx = rem % PD;
    if (y < 2 || y >= 66 || xx < 2 || xx >= 66) g_apad[idx] = 0.f;
}

// ---------------- actv -> apad interior (tf32-rounded) ----------------
__global__ void k_atrans() {
    __shared__ float t[32][33];
    int p0 = blockIdx.x * 32, k0 = blockIdx.y * 32, b = blockIdx.z;
    int tx = threadIdx.x, ty = threadIdx.y;
    for (int r = ty; r < 32; r += 8)
        t[r][tx] = g_actv1[((size_t)(b * PIX + p0 + r)) * 512 + k0 + tx];
    __syncthreads();
    for (int r = ty; r < 32; r += 8) {
        int k = k0 + r, p = p0 + tx;
        int h = p >> 6, w = p & 63;
        g_apad[((size_t)(b * 512 + k) * PD + (h + 2)) * PD + (w + 2)] = tf32r(t[tx][r]);
    }
}

// ---------------- spade conv via mma.sync tf32 ----------------
// CTA: 128 o2 x (4 rows x 64 w); 8 warps = 2M x 4N; warp tile 64 o2 x 64 px.
#define PLA   552            // As plane stride (8*68 + 8 pad)
#define WROW  136            // Ws kc stride (128 + 8 pad)
#define WTILE (8*WROW)       // per-kx
#define WKY   (5*WTILE)      // per ky-group
#define ASBUF (8*PLA)
#define SMEMB ((2*ASBUF + 2*WKY)*4)

__global__ void __launch_bounds__(256, 1)
k_conv_mma(const float* __restrict__ sgb, const float* __restrict__ sbb) {
    extern __shared__ float sm[];
    float* Asm = sm;                 // [2][ASBUF]
    float* Wsm = sm + 2 * ASBUF;     // [2][WKY]

    const int o0 = blockIdx.x * 128;
    const int h0 = blockIdx.y * 4;
    const int b  = blockIdx.z;
    const int tid = threadIdx.x;
    const int lane = tid & 31, wid = tid >> 5;
    const int warpM = wid & 1;
    const int warpN = wid >> 1;          // output row within 4-row tile
    const int tig = lane & 3, gid = lane >> 2;

    const float* apadB = g_apad + (size_t)b * 512 * PD * PD;

    // Ws[(c0+kc)*25 + ky*5+kx][o0..o0+127] -> Wsm[r][kx][kc][o2]
    auto loadWs = [&](int r, int c0, int ky) {
        #pragma unroll
        for (int ii = 0; ii < 5; ii++) {
            int i = ii * 256 + tid;               // 1280 cp ops
            int kx = i >> 8, rem = i & 255;
            int kc = rem >> 5, c4 = rem & 31;
            cpa16(Wsm + r * WKY + kx * WTILE + kc * WROW + c4 * 4,
                  g_WspT + ((size_t)((c0 + kc) * 25 + ky * 5 + kx)) * 512 + o0 + c4 * 4);
        }
    };
    // apad planes c0..c0+7, padded rows h0..h0+7 -> Asm[abf][pl][row][68]
    auto loadAs = [&](int abf, int c0) {
        for (int i = tid; i < 1088; i += 256) {
            int pl = i / 136, rem = i % 136;
            int row = rem / 17, c4 = rem % 17;
            cpa16(Asm + abf * ASBUF + pl * PLA + row * 68 + c4 * 4,
                  apadB + ((size_t)(c0 + pl) * PD + (h0 + row)) * PD + c4 * 4);
        }
    };

    loadAs(0, 0);
    loadWs(0, 0, 0);
    cpa_commit();

    // accumulators with bias baked in
    const int mrow = o0 + warpM * 64 + gid;
    float4 acc[4][8];
    #pragma unroll
    for (int mt = 0; mt < 4; mt++) {
        int r0 = mrow + mt * 16;
        float bx = (r0 < 256) ? sgb[r0] : sbb[r0 - 256];
        int r8 = r0 + 8;
        float bz = (r8 < 256) ? sgb[r8] : sbb[r8 - 256];
        #pragma unroll
        for (int nt = 0; nt < 8; nt++) acc[mt][nt] = make_float4(bx, bx, bz, bz);
    }

    cpa_wait0();
    __syncthreads();

    const int aoff = warpM * 64 + gid;

    for (int cc = 0; cc < 64; cc++) {
        int c0 = cc * 8;
        int abuf = cc & 1;
        #pragma unroll 1
        for (int ky = 0; ky < 5; ky++) {
            int wbuf = (cc * 5 + ky) & 1;
            int kyn = ky + 1, ccn = cc, c0n = c0;
            if (kyn == 5) { kyn = 0; ccn = cc + 1; c0n = c0 + 8; }
            if (ccn < 64) {
                loadWs(wbuf ^ 1, c0n, kyn);
                if (kyn == 0) loadAs(abuf ^ 1, c0n);
            }
            cpa_commit();

            const float* wk = Wsm + wbuf * WKY;
            const float* bbase = Asm + abuf * ASBUF + tig * PLA
                               + (warpN + ky) * 68 + gid;
            #pragma unroll
            for (int kx = 0; kx < 5; kx++) {
                unsigned a[4][4];
                #pragma unroll
                for (int mt = 0; mt < 4; mt++) {
                    const float* p0 = wk + kx * WTILE + tig * WROW + aoff + mt * 16;
                    a[mt][0] = __float_as_uint(p0[0]);
                    a[mt][1] = __float_as_uint(p0[8]);
                    a[mt][2] = __float_as_uint(p0[4 * WROW]);
                    a[mt][3] = __float_as_uint(p0[4 * WROW + 8]);
                }
                const float* bp = bbase + kx;
                #pragma unroll
                for (int nt = 0; nt < 8; nt++) {
                    unsigned b0 = __float_as_uint(bp[nt * 8]);
                    unsigned b1 = __float_as_uint(bp[nt * 8 + 4 * PLA]);
                    #pragma unroll
                    for (int mt = 0; mt < 4; mt++)
                        mma_tf32(acc[mt][nt], a[mt], b0, b1);
                }
            }
            cpa_wait0();
            __syncthreads();
        }
    }

    // epilogue: rows = o2 channels, cols = w
    #pragma unroll
    for (int mt = 0; mt < 4; mt++) {
        int r0 = mrow + mt * 16;
        size_t base0 = (((size_t)b * 512 + r0) * HH + (h0 + warpN)) * WW;
        size_t base1 = (((size_t)b * 512 + r0 + 8) * HH + (h0 + warpN)) * WW;
        #pragma unroll
        for (int nt = 0; nt < 8; nt++) {
            int w = nt * 8 + tig * 2;
            *(float2*)&g_gsp[base0 + w] = make_float2(acc[mt][nt].x, acc[mt][nt].y);
            *(float2*)&g_gsp[base1 + w] = make_float2(acc[mt][nt].z, acc[mt][nt].w);
        }
    }
}

// ---------------- final blend ----------------
__global__ void k_final(const float* __restrict__ x,
                        const float* __restrict__ cgb, const float* __restrict__ cbb,
                        const float* __restrict__ bg, const float* __restrict__ bb,
                        float* __restrict__ out) {
    int bh = blockIdx.x;
    int b = bh >> 6, h = bh & 63;
    int tid = threadIdx.x;
    int w = tid & 63, os = tid >> 6;
    float ga = 1.f / (1.f + expf(-bg[0]));
    float ba = 1.f / (1.f + expf(-bb[0]));
    size_t gi = ((size_t)(b * PIX + h * WW + w)) * 512;
    for (int oc = 0; oc < NC; oc += 4) {
        int o = oc + os;
        float m = g_mean[b * NC + o], rs = g_rstd[b * NC + o];
        size_t xi = ((size_t)(b * NC + o) * HH + h) * WW + w;
        float nv = (x[xi] - m) * rs;
        float gs = g_gsp[((size_t)(b * 512 + o) * HH + h) * WW + w];
        float bs = g_gsp[((size_t)(b * 512 + o + 256) * HH + h) * WW + w];
        float gav = g_gavg[gi + o] + cgb[o];
        float bav = g_gavg[gi + 256 + o] + cbb[o];
        float gf = ga * gav + (1.f - ga) * gs;
        float bf = ba * bav + (1.f - ba) * bs;
        out[xi] = nv * (1.f + gf) + bf;
    }
}

// ---------------- launch ----------------
extern "C" void kernel_launch(void* const* d_in, const int* in_sizes, int n_in,
                              void* d_out, int out_size) {
    const float* x      = (const float*)d_in[0];
    const float* segmap = (const float*)d_in[1];
    const float* style  = (const float*)d_in[2];
    const float* fc_w   = (const float*)d_in[3];
    const float* fc_b   = (const float*)d_in[4];
    const float* cgw    = (const float*)d_in[5];
    const float* cgb    = (const float*)d_in[6];
    const float* cbw    = (const float*)d_in[7];
    const float* cbb    = (const float*)d_in[8];
    const float* ssw    = (const float*)d_in[9];
    const float* ssb    = (const float*)d_in[10];
    const float* sgw    = (const float*)d_in[11];
    const float* sgb    = (const float*)d_in[12];
    const float* sbw    = (const float*)d_in[13];
    const float* sbb    = (const float*)d_in[14];
    const float* bg     = (const float*)d_in[15];
    const float* bb     = (const float*)d_in[16];
    float* out = (float*)d_out;

    float* pWshT; cudaGetSymbolAddress((void**)&pWshT, g_WshT);
    float* pWspT; cudaGetSymbolAddress((void**)&pWspT, g_WspT);
    float* pWgbT; cudaGetSymbolAddress((void**)&pWgbT, g_WgbT);

    cudaFuncSetAttribute(k_conv_mma, cudaFuncAttributeMaxDynamicSharedMemorySize, SMEMB);

    dim3 tb(32, 8);

    k_stats<<<NB * NC, 256>>>(x);
    k_labels<<<(NB * PD * PD + 255) / 256, 256>>>(segmap);
    k_mu<<<NB * LNC, 256>>>(style, fc_w, fc_b);

    k_transpose<<<dim3(15, 16), tb>>>(ssw, pWshT, 512, 475, 512, 0, 0, 0);
    k_transpose<<<dim3(400, 8), tb>>>(sgw, pWspT, 256, 12800, 512, 0, 0, 1);
    k_transpose<<<dim3(400, 8), tb>>>(sbw, pWspT, 256, 12800, 512, 256, 0, 1);
    k_transpose<<<dim3(400, 8), tb>>>(cgw, pWgbT, 256, 12800, 512, 0, 1, 0);
    k_transpose<<<dim3(400, 8), tb>>>(cbw, pWgbT, 256, 12800, 512, 256, 1, 0);

    k_G<<<dim3(19, 25), 128>>>();
    k_gather<<<NB * HH, 256>>>();
    k_actv<<<NB * HH, 256>>>(ssb);
    k_border<<<(NB * 512 * PD * PD + 255) / 256, 256>>>();
    k_atrans<<<dim3(PIX / 32, 512 / 32, NB), tb>>>();
    k_conv_mma<<<dim3(4, 16, NB), 256, SMEMB>>>(sgb, sbb);
    k_final<<<NB * HH, 256>>>(x, cgb, cbb, bg, bb, out);
}

// round 5
// speedup vs baseline: 5.2698x; 1.6269x over previous
#include <cuda_runtime.h>
#include <math.h>

#define NB   8
#define NC   256
#define LNC  19
#define HH   64
#define WW   64
#define SL   512
#define PIX  (HH*WW)
#define PD   68

typedef unsigned long long ull;

// ---------------- scratch ----------------
static __device__ float    g_mean[NB*NC];
static __device__ float    g_rstd[NB*NC];
static __device__ int      g_labp[NB*PD*PD];
static __device__ float    g_mu[NB*LNC*SL];
static __device__ float    g_WshT[475*512];          // [j*25+i][k]
static __device__ float    g_WspT[12800*512];        // [c*25+d][o2] fp32 staging
static __device__ unsigned g_Wsp2[6400*512];         // [cp*25+d][o2] bf16x2 (c pair)
static __device__ float    g_WgbT[12800*512];        // [d*512+e][o2]
static __device__ float    g_G[NB*LNC*25*512];
static __device__ float    g_gavg[NB*PIX*512];
static __device__ float    g_actv1[NB*PIX*512];
static __device__ unsigned g_apad2[NB*256*PD*PD];    // [b][cp][y][x] bf16x2, zero-padded
static __device__ float    g_gsp[NB*512*PIX];

// ---------------- helpers ----------------
__device__ __forceinline__ void fma_f32x2(ull& d, ull a, ull b) {
    asm("fma.rn.f32x2 %0, %1, %2, %0;" : "+l"(d) : "l"(a), "l"(b));
}
__device__ __forceinline__ ull pack_dup(float x) {
    ull r; asm("mov.b64 %0, {%1, %1};" : "=l"(r) : "f"(x)); return r;
}
__device__ __forceinline__ ull pack2(float lo, float hi) {
    ull r; asm("mov.b64 %0, {%1, %2};" : "=l"(r) : "f"(lo), "f"(hi)); return r;
}
__device__ __forceinline__ void unpack2(ull v, float& lo, float& hi) {
    asm("mov.b64 {%0, %1}, %2;" : "=f"(lo), "=f"(hi) : "l"(v));
}
// pack two floats into bf16x2: lo -> bits[0:16), hi -> bits[16:32)
__device__ __forceinline__ unsigned bf16pack(float lo, float hi) {
    unsigned r;
    asm("cvt.rn.bf16x2.f32 %0, %1, %2;" : "=r"(r) : "f"(hi), "f"(lo));
    return r;
}
__device__ __forceinline__ void mma_bf16(float4& d, const unsigned* a,
                                         unsigned b0, unsigned b1) {
    asm("mma.sync.aligned.m16n8k16.row.col.f32.bf16.bf16.f32 "
        "{%0,%1,%2,%3}, {%4,%5,%6,%7}, {%8,%9}, {%0,%1,%2,%3};"
        : "+f"(d.x), "+f"(d.y), "+f"(d.z), "+f"(d.w)
        : "r"(a[0]), "r"(a[1]), "r"(a[2]), "r"(a[3]), "r"(b0), "r"(b1));
}
__device__ __forceinline__ void cpa16(void* dst, const void* src) {
    unsigned s = (unsigned)__cvta_generic_to_shared(dst);
    asm volatile("cp.async.cg.shared.global [%0], [%1], 16;" :: "r"(s), "l"(src) : "memory");
}
__device__ __forceinline__ void cpa_commit() {
    asm volatile("cp.async.commit_group;" ::: "memory");
}
__device__ __forceinline__ void cpa_wait0() {
    asm volatile("cp.async.wait_group 0;" ::: "memory");
}

// ---------------- instance norm stats ----------------
__global__ void k_stats(const float* __restrict__ x) {
    int bc = blockIdx.x;
    const float* p = x + (size_t)bc * PIX;
    float s = 0.f, ss = 0.f;
    for (int i = threadIdx.x; i < PIX; i += 256) { float v = p[i]; s += v; ss += v * v; }
    __shared__ float sh[512];
    sh[threadIdx.x] = s; sh[256 + threadIdx.x] = ss; __syncthreads();
    for (int off = 128; off > 0; off >>= 1) {
        if (threadIdx.x < off) { sh[threadIdx.x] += sh[threadIdx.x + off]; sh[256 + threadIdx.x] += sh[256 + threadIdx.x + off]; }
        __syncthreads();
    }
    if (threadIdx.x == 0) {
        float m = sh[0] / (float)PIX;
        float v = sh[256] / (float)PIX - m * m;
        g_mean[bc] = m; g_rstd[bc] = rsqrtf(v + 1e-5f);
    }
}

// ---------------- padded label map ----------------
__global__ void k_labels(const float* __restrict__ segmap) {
    int idx = blockIdx.x * 256 + threadIdx.x;
    if (idx >= NB * PD * PD) return;
    int b = idx / (PD * PD), rem = idx % (PD * PD);
    int y = rem / PD, xx = rem % PD;
    int lab = -1;
    if (y >= 2 && y < 66 && xx >= 2 && xx < 66) {
        int h = y - 2, w = xx - 2;
        for (int j = LNC - 1; j >= 0; j--) {
            if (segmap[((b * LNC + j) * HH + h) * WW + w] > 0.f) { lab = j; break; }
        }
    }
    g_labp[idx] = lab;
}

// ---------------- mu ----------------
__global__ void k_mu(const float* __restrict__ style, const float* __restrict__ fc_w,
                     const float* __restrict__ fc_b) {
    int bj = blockIdx.x;
    int b = bj / LNC, j = bj % LNC;
    int tid = threadIdx.x, lane = tid & 31, wid = tid >> 5;
    __shared__ float sc[SL];
    for (int i = tid; i < SL; i += 256) sc[i] = style[(b * LNC + j) * SL + i];
    __syncthreads();
    for (int e = wid; e < SL; e += 8) {
        const float* row = fc_w + ((size_t)(j * SL + e)) * SL;
        float acc = 0.f;
        for (int d = lane; d < SL; d += 32) acc += sc[d] * row[d];
        for (int off = 16; off; off >>= 1) acc += __shfl_xor_sync(0xffffffffu, acc, off);
        if (lane == 0) {
            float v = acc + fc_b[j * SL + e];
            g_mu[(b * LNC + j) * SL + e] = fmaxf(v, 0.f);
        }
    }
}

// ---------------- tiled transpose ----------------
__global__ void k_transpose(const float* __restrict__ in, float* __restrict__ out,
                            int M, int N, int outStride, int colOff, int mode) {
    __shared__ float t[32][33];
    int n0 = blockIdx.x * 32, m0 = blockIdx.y * 32;
    int tx = threadIdx.x, ty = threadIdx.y;
    for (int r = ty; r < 32; r += 8) {
        int m = m0 + r, n = n0 + tx;
        t[r][tx] = (m < M && n < N) ? in[(size_t)m * N + n] : 0.f;
    }
    __syncthreads();
    for (int r = ty; r < 32; r += 8) {
        int n = n0 + r, m = m0 + tx;
        if (n < N && m < M) {
            int orow = (mode == 1) ? (n % 25) * 512 + (n / 25) : n;
            out[(size_t)orow * outStride + colOff + m] = t[tx][r];
        }
    }
}

// ---------------- pack WspT channel pairs into bf16x2 ----------------
__global__ void k_wpack() {
    int idx = blockIdx.x * 256 + threadIdx.x;
    if (idx >= 6400 * 512) return;
    int row = idx >> 9, o = idx & 511;
    int cp = row / 25, d = row % 25;
    float lo = g_WspT[((size_t)(2 * cp * 25 + d)) * 512 + o];
    float hi = g_WspT[((size_t)((2 * cp + 1) * 25 + d)) * 512 + o];
    g_Wsp2[idx] = bf16pack(lo, hi);
}

// ---------------- k_G (FFMA2, 8-bj blocking) ----------------
__global__ void k_G() {
    __shared__ float mus[8 * SL];
    int bj0 = blockIdx.x * 8;
    int off = blockIdx.y;
    int tid = threadIdx.x;
    for (int i = tid; i < 8 * SL; i += 128) mus[i] = g_mu[bj0 * SL + i];
    __syncthreads();
    ull acc[8][2];
    #pragma unroll
    for (int j = 0; j < 8; j++) { acc[j][0] = 0ull; acc[j][1] = 0ull; }
    const float4* wrow = (const float4*)(g_WgbT + (size_t)off * 512 * 512);
    for (int e = 0; e < 512; e++) {
        float4 w = wrow[e * 128 + tid];
        ull wp0 = pack2(w.x, w.y), wp1 = pack2(w.z, w.w);
        #pragma unroll
        for (int j = 0; j < 8; j++) {
            ull m = pack_dup(mus[j * 512 + e]);
            fma_f32x2(acc[j][0], wp0, m);
            fma_f32x2(acc[j][1], wp1, m);
        }
    }
    #pragma unroll
    for (int j = 0; j < 8; j++) {
        float4 o;
        unpack2(acc[j][0], o.x, o.y);
        unpack2(acc[j][1], o.z, o.w);
        *(float4*)&g_G[((size_t)((bj0 + j) * 25 + off)) * 512 + 4 * tid] = o;
    }
}

// ---------------- fused gather (gavg) + actv ----------------
__global__ void k_gact(const float* __restrict__ sh_b) {
    int bh = blockIdx.x;
    int b = bh >> 6, h = bh & 63;
    int tid = threadIdx.x;
    __shared__ int labw[5 * PD];
    for (int i = tid; i < 5 * PD; i += 256)
        labw[i] = g_labp[(b * PD + h + i / PD) * PD + (i % PD)];
    __syncthreads();
    float bias0 = sh_b[tid], bias1 = sh_b[tid + 256];
    for (int w = 0; w < WW; w++) {
        float g0 = 0.f, g1 = 0.f, a0 = bias0, a1 = bias1;
        #pragma unroll
        for (int i = 0; i < 25; i++) {
            int j = labw[(i / 5) * PD + w + (i % 5)];
            if (j >= 0) {
                const float* gg = g_G + ((size_t)((b * LNC + j) * 25 + i)) * 512;
                const float* ws = g_WshT + ((size_t)(j * 25 + i)) * 512;
                g0 += gg[tid]; g1 += gg[tid + 256];
                a0 += ws[tid]; a1 += ws[tid + 256];
            }
        }
        float* og = g_gavg + ((size_t)(b * PIX + h * WW + w)) * 512;
        og[tid] = g0; og[tid + 256] = g1;
        float* oa = g_actv1 + ((size_t)(b * PIX + h * WW + w)) * 512;
        oa[tid] = fmaxf(a0, 0.f); oa[tid + 256] = fmaxf(a1, 0.f);
    }
}

// ---------------- zero padded borders of apad2 ----------------
__global__ void k_border() {
    int idx = blockIdx.x * 256 + threadIdx.x;
    if (idx >= NB * 256 * PD * PD) return;
    int rem = idx % (PD * PD);
    int y = rem / PD, xx = rem % PD;
    if (y < 2 || y >= 66 || xx < 2 || xx >= 66) g_apad2[idx] = 0u;
}

// ---------------- actv -> apad2 interior (bf16x2 channel pairs) ----------------
__global__ void k_atrans() {
    __shared__ float t[32][33];
    int p0 = blockIdx.x * 32, k0 = blockIdx.y * 32, b = blockIdx.z;
    int tx = threadIdx.x, ty = threadIdx.y;
    for (int r = ty; r < 32; r += 8)
        t[r][tx] = g_actv1[((size_t)(b * PIX + p0 + r)) * 512 + k0 + tx];
    __syncthreads();
    for (int r = ty; r < 16; r += 8) {
        int cp = (k0 >> 1) + r;
        int p = p0 + tx;
        int h = p >> 6, w = p & 63;
        g_apad2[((size_t)(b * 256 + cp) * PD + (h + 2)) * PD + (w + 2)] =
            bf16pack(t[tx][2 * r], t[tx][2 * r + 1]);
    }
}

// ---------------- spade conv via mma.sync bf16 m16n8k16 ----------------
// CTA: 128 o2 x (4 rows x 64 w); 8 warps = 2M x 4N; warp tile 64 o2 x 64 px.
// K loop: 32 chunks of 16 channels (8 bf16x2 pairs), 25 offsets each.
#define PLA   552            // As plane stride in words (8*68 + 8 pad)
#define WROW  136            // Ws cpair stride (128 + 8 pad)
#define WTILE (8*WROW)       // per-kx: 8 cpairs
#define WKY   (5*WTILE)      // per ky-group
#define ASBUF (8*PLA)
#define SMEMB ((2*ASBUF + 2*WKY)*4)

__global__ void __launch_bounds__(256, 1)
k_conv_mma(const float* __restrict__ sgb, const float* __restrict__ sbb) {
    extern __shared__ unsigned sm[];
    unsigned* Asm = sm;                 // [2][ASBUF]
    unsigned* Wsm = sm + 2 * ASBUF;     // [2][WKY]

    const int o0 = blockIdx.x * 128;
    const int h0 = blockIdx.y * 4;
    const int b  = blockIdx.z;
    const int tid = threadIdx.x;
    const int lane = tid & 31, wid = tid >> 5;
    const int warpM = wid & 1;
    const int warpN = wid >> 1;
    const int tig = lane & 3, gid = lane >> 2;

    const unsigned* apadB = g_apad2 + (size_t)b * 256 * PD * PD;

    // g_Wsp2[(cp0+kc)*25 + ky*5+kx][o0..o0+127] -> Wsm[r][kx][kc][o2]
    auto loadWs = [&](int r, int cp0, int ky) {
        #pragma unroll
        for (int ii = 0; ii < 5; ii++) {
            int i = ii * 256 + tid;               // 1280 cp ops
            int kx = i >> 8, rem = i & 255;
            int kc = rem >> 5, c4 = rem & 31;
            cpa16(Wsm + r * WKY + kx * WTILE + kc * WROW + c4 * 4,
                  g_Wsp2 + ((size_t)((cp0 + kc) * 25 + ky * 5 + kx)) * 512 + o0 + c4 * 4);
        }
    };
    // apad2 cpairs cp0..cp0+7, rows h0..h0+7 -> Asm[abf][pl][row][68]
    auto loadAs = [&](int abf, int cp0) {
        for (int i = tid; i < 1088; i += 256) {
            int pl = i / 136, rem = i % 136;
            int row = rem / 17, c4 = rem % 17;
            cpa16(Asm + abf * ASBUF + pl * PLA + row * 68 + c4 * 4,
                  apadB + ((size_t)(cp0 + pl) * PD + (h0 + row)) * PD + c4 * 4);
        }
    };

    loadAs(0, 0);
    loadWs(0, 0, 0);
    cpa_commit();

    // accumulators with bias baked in
    const int mrow = o0 + warpM * 64 + gid;
    float4 acc[4][8];
    #pragma unroll
    for (int mt = 0; mt < 4; mt++) {
        int r0 = mrow + mt * 16;
        float bx = (r0 < 256) ? sgb[r0] : sbb[r0 - 256];
        int r8 = r0 + 8;
        float bz = (r8 < 256) ? sgb[r8] : sbb[r8 - 256];
        #pragma unroll
        for (int nt = 0; nt < 8; nt++) acc[mt][nt] = make_float4(bx, bx, bz, bz);
    }

    cpa_wait0();
    __syncthreads();

    const int aoff = warpM * 64 + gid;

    for (int cc = 0; cc < 32; cc++) {
        int cp0 = cc * 8;
        int abuf = cc & 1;
        #pragma unroll 1
        for (int ky = 0; ky < 5; ky++) {
            int wbuf = (cc * 5 + ky) & 1;
            int kyn = ky + 1, ccn = cc, cp0n = cp0;
            if (kyn == 5) { kyn = 0; ccn = cc + 1; cp0n = cp0 + 8; }
            if (ccn < 32) {
                loadWs(wbuf ^ 1, cp0n, kyn);
                if (kyn == 0) loadAs(abuf ^ 1, cp0n);
            }
            cpa_commit();

            const unsigned* wk = Wsm + wbuf * WKY;
            const unsigned* bbase = Asm + abuf * ASBUF + tig * PLA
                                  + (warpN + ky) * 68 + gid;
            #pragma unroll
            for (int kx = 0; kx < 5; kx++) {
                unsigned a[4][4];
                #pragma unroll
                for (int mt = 0; mt < 4; mt++) {
                    const unsigned* p0 = wk + kx * WTILE + tig * WROW + aoff + mt * 16;
                    a[mt][0] = p0[0];            // cpair tig,  row gid
                    a[mt][1] = p0[8];            // cpair tig,  row gid+8
                    a[mt][2] = p0[4 * WROW];     // cpair tig+4, row gid
                    a[mt][3] = p0[4 * WROW + 8]; // cpair tig+4, row gid+8
                }
                const unsigned* bp = bbase + kx;
                #pragma unroll
                for (int nt = 0; nt < 8; nt++) {
                    unsigned b0 = bp[nt * 8];
                    unsigned b1 = bp[nt * 8 + 4 * PLA];
                    #pragma unroll
                    for (int mt = 0; mt < 4; mt++)
                        mma_bf16(acc[mt][nt], a[mt], b0, b1);
                }
            }
            cpa_wait0();
            __syncthreads();
        }
    }

    // epilogue
    #pragma unroll
    for (int mt = 0; mt < 4; mt++) {
        int r0 = mrow + mt * 16;
        size_t base0 = (((size_t)b * 512 + r0) * HH + (h0 + warpN)) * WW;
        size_t base1 = (((size_t)b * 512 + r0 + 8) * HH + (h0 + warpN)) * WW;
        #pragma unroll
        for (int nt = 0; nt < 8; nt++) {
            int w = nt * 8 + tig * 2;
            *(float2*)&g_gsp[base0 + w] = make_float2(acc[mt][nt].x, acc[mt][nt].y);
            *(float2*)&g_gsp[base1 + w] = make_float2(acc[mt][nt].z, acc[mt][nt].w);
        }
    }
}

// ---------------- final blend ----------------
__global__ void k_final(const float* __restrict__ x,
                        const float* __restrict__ cgb, const float* __restrict__ cbb,
                        const float* __restrict__ bg, const float* __restrict__ bb,
                        float* __restrict__ out) {
    int bh = blockIdx.x;
    int b = bh >> 6, h = bh & 63;
    int tid = threadIdx.x;
    int w = tid & 63, os = tid >> 6;
    float ga = 1.f / (1.f + expf(-bg[0]));
    float ba = 1.f / (1.f + expf(-bb[0]));
    size_t gi = ((size_t)(b * PIX + h * WW + w)) * 512;
    for (int oc = 0; oc < NC; oc += 4) {
        int o = oc + os;
        float m = g_mean[b * NC + o], rs = g_rstd[b * NC + o];
        size_t xi = ((size_t)(b * NC + o) * HH + h) * WW + w;
        float nv = (x[xi] - m) * rs;
        float gs = g_gsp[((size_t)(b * 512 + o) * HH + h) * WW + w];
        float bs = g_gsp[((size_t)(b * 512 + o + 256) * HH + h) * WW + w];
        float gav = g_gavg[gi + o] + cgb[o];
        float bav = g_gavg[gi + 256 + o] + cbb[o];
        float gf = ga * gav + (1.f - ga) * gs;
        float bf = ba * bav + (1.f - ba) * bs;
        out[xi] = nv * (1.f + gf) + bf;
    }
}

// ---------------- launch ----------------
extern "C" void kernel_launch(void* const* d_in, const int* in_sizes, int n_in,
                              void* d_out, int out_size) {
    const float* x      = (const float*)d_in[0];
    const float* segmap = (const float*)d_in[1];
    const float* style  = (const float*)d_in[2];
    const float* fc_w   = (const float*)d_in[3];
    const float* fc_b   = (const float*)d_in[4];
    const float* cgw    = (const float*)d_in[5];
    const float* cgb    = (const float*)d_in[6];
    const float* cbw    = (const float*)d_in[7];
    const float* cbb    = (const float*)d_in[8];
    const float* ssw    = (const float*)d_in[9];
    const float* ssb    = (const float*)d_in[10];
    const float* sgw    = (const float*)d_in[11];
    const float* sgb    = (const float*)d_in[12];
    const float* sbw    = (const float*)d_in[13];
    const float* sbb    = (const float*)d_in[14];
    const float* bg     = (const float*)d_in[15];
    const float* bb     = (const float*)d_in[16];
    float* out = (float*)d_out;

    float* pWshT; cudaGetSymbolAddress((void**)&pWshT, g_WshT);
    float* pWspT; cudaGetSymbolAddress((void**)&pWspT, g_WspT);
    float* pWgbT; cudaGetSymbolAddress((void**)&pWgbT, g_WgbT);

    cudaFuncSetAttribute(k_conv_mma, cudaFuncAttributeMaxDynamicSharedMemorySize, SMEMB);

    dim3 tb(32, 8);

    k_stats<<<NB * NC, 256>>>(x);
    k_labels<<<(NB * PD * PD + 255) / 256, 256>>>(segmap);
    k_mu<<<NB * LNC, 256>>>(style, fc_w, fc_b);

    k_transpose<<<dim3(15, 16), tb>>>(ssw, pWshT, 512, 475, 512, 0, 0);
    k_transpose<<<dim3(400, 8), tb>>>(sgw, pWspT, 256, 12800, 512, 0, 0);
    k_transpose<<<dim3(400, 8), tb>>>(sbw, pWspT, 256, 12800, 512, 256, 0);
    k_wpack<<<(6400 * 512 + 255) / 256, 256>>>();
    k_transpose<<<dim3(400, 8), tb>>>(cgw, pWgbT, 256, 12800, 512, 0, 1);
    k_transpose<<<dim3(400, 8), tb>>>(cbw, pWgbT, 256, 12800, 512, 256, 1);

    k_G<<<dim3(19, 25), 128>>>();
    k_gact<<<NB * HH, 256>>>(ssb);
    k_border<<<(NB * 256 * PD * PD + 255) / 256, 256>>>();
    k_atrans<<<dim3(PIX / 32, 512 / 32, NB), tb>>>();
    k_conv_mma<<<dim3(4, 16, NB), 256, SMEMB>>>(sgb, sbb);
    k_final<<<NB * HH, 256>>>(x, cgb, cbb, bg, bb, out);
}